// round 1
// baseline (speedup 1.0000x reference)
#include <cuda_runtime.h>
#include <cfloat>
#include <math.h>

#define Bn 64
#define Dn 256
#define Ln 4096
#define DKn 128
#define LN_EPS 1e-6f
#define EPS_CLIP 1e-10f

// ---------------- scratch (static device globals; no allocation) ----------------
__device__ float g_mu[Bn * Ln];
__device__ float g_rsig[Bn * Ln];
__device__ float g_scores[Bn * Ln];
__device__ float g_w[Bn * Ln];
__device__ float g_U1[Bn * Dn], g_U2[Bn * Dn], g_U3[Bn * Dn];
__device__ float g_R1[Bn * Dn], g_R2[Bn * Dn], g_R3[Bn * Dn];
__device__ float g_gp[Bn * Dn];
__device__ float g_corr[Bn * Dn];
__device__ float g_SMR[Bn], g_SM2R2[Bn], g_Cb[Bn], g_Gp[Bn], g_A[Bn], g_M2[Bn];

// ---------------- reduction helpers ----------------
__device__ __forceinline__ float warpSum(float v) {
#pragma unroll
    for (int o = 16; o; o >>= 1) v += __shfl_xor_sync(0xffffffffu, v, o);
    return v;
}
__device__ __forceinline__ float warpMax(float v) {
#pragma unroll
    for (int o = 16; o; o >>= 1) v = fmaxf(v, __shfl_xor_sync(0xffffffffu, v, o));
    return v;
}
// block-wide sum, result broadcast to all threads
__device__ __forceinline__ float bSum(float v) {
    __shared__ float sh[32];
    int lane = threadIdx.x & 31, w = threadIdx.x >> 5;
    int nw = (blockDim.x + 31) >> 5;
    v = warpSum(v);
    if (lane == 0) sh[w] = v;
    __syncthreads();
    if (w == 0) {
        float x = (lane < nw) ? sh[lane] : 0.0f;
        x = warpSum(x);
        if (lane == 0) sh[0] = x;
    }
    __syncthreads();
    float r = sh[0];
    __syncthreads();
    return r;
}
__device__ __forceinline__ float bMax(float v) {
    __shared__ float sh[32];
    int lane = threadIdx.x & 31, w = threadIdx.x >> 5;
    int nw = (blockDim.x + 31) >> 5;
    v = warpMax(v);
    if (lane == 0) sh[w] = v;
    __syncthreads();
    if (w == 0) {
        float x = (lane < nw) ? sh[lane] : -FLT_MAX;
        x = warpMax(x);
        if (lane == 0) sh[0] = x;
    }
    __syncthreads();
    float r = sh[0];
    __syncthreads();
    return r;
}

// ---------------- 1. LayerNorm stats per (b,l): mu, rsig ----------------
// thread per l (256 consecutive l per block) -> every load is a coalesced 128B warp read
__global__ void k_ln_stats(const float* __restrict__ v) {
    int b = blockIdx.x / (Ln / 256);
    int l = (blockIdx.x % (Ln / 256)) * 256 + threadIdx.x;
    const float* col = v + (size_t)b * Dn * Ln + l;
    float s = 0.f, s2 = 0.f;
#pragma unroll 8
    for (int d = 0; d < Dn; d++) {
        float x = col[(size_t)d * Ln];
        s += x;
        s2 += x * x;
    }
    float mu = s * (1.0f / Dn);
    float var = s2 * (1.0f / Dn) - mu * mu;
    float rs = rsqrtf(var + LN_EPS);
    g_mu[b * Ln + l] = mu;
    g_rsig[b * Ln + l] = rs;
}

// ---------------- 2. per-batch scalars over l: SMR = sum(mu*rsig), SM2R2 = sum(mu^2*rsig^2)
__global__ void k_scalars() {
    int b = blockIdx.x;
    float smr = 0.f, s22 = 0.f;
    for (int l = threadIdx.x; l < Ln; l += blockDim.x) {
        float a = g_mu[b * Ln + l], r = g_rsig[b * Ln + l];
        smr += a * r;
        s22 += a * a * r * r;
    }
    smr = bSum(smr);
    s22 = bSum(s22);
    if (threadIdx.x == 0) { g_SMR[b] = smr; g_SM2R2[b] = s22; }
}

// ---------------- 3/7. weighted row sums over l, one block per (b,d) row ----------------
// mode 0: wl=1     -> U1=sum(v*r), U2=sum(v^2*r^2), U3=sum(v*mu*r^2)   (for batch mean/std)
// mode 1: wl=w[l]  -> R1=sum(v*w*r), R2=sum(v^2*w*r^2), R3=sum(v*w*mu*r^2) (for attention stats)
__global__ void k_rowsums(const float* __restrict__ v, int mode) {
    int row = blockIdx.x;          // b*Dn + d
    int b = row >> 8;              // Dn == 256
    const float* vp = v + (size_t)row * Ln;
    const float* ap = g_mu + b * Ln;
    const float* rp = g_rsig + b * Ln;
    const float* wp = g_w + b * Ln;
    float s1 = 0.f, s2 = 0.f, s3 = 0.f;
#pragma unroll 4
    for (int l = threadIdx.x; l < Ln; l += 256) {
        float x = vp[l], a = ap[l], r = rp[l];
        float wl = mode ? wp[l] : 1.0f;
        float c1 = wl * r;
        float c2 = c1 * r;
        float c3 = c2 * a;
        s1 = fmaf(x, c1, s1);
        s2 = fmaf(x * x, c2, s2);
        s3 = fmaf(x, c3, s3);
    }
    s1 = bSum(s1);
    s2 = bSum(s2);
    s3 = bSum(s3);
    if (threadIdx.x == 0) {
        if (mode) { g_R1[row] = s1; g_R2[row] = s2; g_R3[row] = s3; }
        else      { g_U1[row] = s1; g_U2[row] = s2; g_U3[row] = s3; }
    }
}

// ---------------- 4. per batch: mean/std over L, q = wq@[mean;std], p = wk^T q ----------------
__global__ void k_qp(const float* __restrict__ wk, const float* __restrict__ wq,
                     const float* __restrict__ ln_g, const float* __restrict__ ln_b) {
    int b = blockIdx.x;
    int t = threadIdx.x;  // 256 threads
    __shared__ float ms[2 * Dn];
    __shared__ float qv[DKn];
    float smr = g_SMR[b], sm2r2 = g_SM2R2[b];
    {
        int d = t;
        float g = ln_g[d], be = ln_b[d];
        float U1 = g_U1[b * Dn + d], U2 = g_U2[b * Dn + d], U3 = g_U3[b * Dn + d];
        float S1 = g * (U1 - smr) + (float)Ln * be;
        float S2 = g * g * (U2 - 2.0f * U3 + sm2r2) + 2.0f * g * be * (U1 - smr) + (float)Ln * be * be;
        float mean = S1 * (1.0f / Ln);
        float var = S2 * (1.0f / Ln) - mean * mean;
        float sd = sqrtf(fmaxf(var, EPS_CLIP));
        ms[d] = mean;
        ms[Dn + d] = sd;
    }
    __syncthreads();
    if (t < DKn) {
        float acc = 0.f;
        const float* wr = wq + (size_t)t * 2 * Dn;
#pragma unroll 8
        for (int e = 0; e < 2 * Dn; e++) acc = fmaf(wr[e], ms[e], acc);
        qv[t] = acc;
    }
    __syncthreads();
    float p = 0.f;
    {
        int d = t;
#pragma unroll 8
        for (int k2 = 0; k2 < DKn; k2++) p = fmaf(wk[k2 * Dn + d], qv[k2], p);
        p *= rsqrtf((float)DKn);  // fold 1/sqrt(DK) into p
    }
    float gp = ln_g[t] * p;
    g_gp[b * Dn + t] = gp;
    float cb = bSum(ln_b[t] * p);
    float gpsum = bSum(gp);
    if (t == 0) { g_Cb[b] = cb; g_Gp[b] = gpsum; }
}

// ---------------- 5. scores[b,l] = rsig*(sum_d v[b,d,l]*gp[b,d] - mu*Gp) + Cb ----------------
__global__ void k_scores(const float* __restrict__ v) {
    __shared__ float sgp[Dn];
    int b = blockIdx.x / (Ln / 256);
    int l = (blockIdx.x % (Ln / 256)) * 256 + threadIdx.x;
    sgp[threadIdx.x] = g_gp[b * Dn + threadIdx.x];  // blockDim == Dn == 256
    __syncthreads();
    const float* col = v + (size_t)b * Dn * Ln + l;
    float acc = 0.f;
#pragma unroll 8
    for (int d = 0; d < Dn; d++) acc = fmaf(col[(size_t)d * Ln], sgp[d], acc);
    float a = g_mu[b * Ln + l], r = g_rsig[b * Ln + l];
    g_scores[b * Ln + l] = r * (acc - a * g_Gp[b]) + g_Cb[b];
}

// ---------------- 6. softmax over L per batch; also A = sum(w*mu*rsig), M2 = sum(w*mu^2*rsig^2)
__global__ void k_softmax() {
    int b = blockIdx.x;
    int t = threadIdx.x;  // 1024 threads, 4 elems each
    float s[4];
    float m = -FLT_MAX;
#pragma unroll
    for (int i = 0; i < 4; i++) {
        s[i] = g_scores[b * Ln + i * 1024 + t];
        m = fmaxf(m, s[i]);
    }
    float M = bMax(m);
    float e[4];
    float se = 0.f, sar = 0.f, sa2 = 0.f;
#pragma unroll
    for (int i = 0; i < 4; i++) {
        e[i] = __expf(s[i] - M);
        se += e[i];
        int l = i * 1024 + t;
        float a = g_mu[b * Ln + l], r = g_rsig[b * Ln + l];
        sar = fmaf(e[i], a * r, sar);
        sa2 = fmaf(e[i], a * a * r * r, sa2);
    }
    float SE = bSum(se);
    float SAR = bSum(sar);
    float SA2 = bSum(sa2);
    float inv = 1.0f / SE;
#pragma unroll
    for (int i = 0; i < 4; i++) g_w[b * Ln + i * 1024 + t] = e[i] * inv;
    if (t == 0) { g_A[b] = SAR * inv; g_M2[b] = SA2 * inv; }
}

// ---------------- 8. att_mean/att_std -> corr (for output) and skip_conn (second output)
__global__ void k_finalize(const float* __restrict__ fcq_w, const float* __restrict__ fc_w,
                           const float* __restrict__ fc_b, const float* __restrict__ ln_g,
                           const float* __restrict__ ln_b, float* __restrict__ out) {
    int b = blockIdx.x;
    int t = threadIdx.x;  // 256
    __shared__ float am[Dn], as[Dn];
    {
        int d = t;
        float g = ln_g[d], be = ln_b[d];
        float R1 = g_R1[b * Dn + d], R2 = g_R2[b * Dn + d], R3 = g_R3[b * Dn + d];
        float A = g_A[b], M2 = g_M2[b];
        float mean = g * (R1 - A) + be;                 // att_mean (sum of weights == 1)
        float E2 = g * g * (R2 - 2.0f * R3 + M2) + 2.0f * g * be * (R1 - A) + be * be;  // E[xn^2]_w
        float var = E2 - mean * mean;
        am[d] = mean;
        as[d] = sqrtf(fmaxf(var, EPS_CLIP));
    }
    __syncthreads();
    {
        int o = t;
        float c = 0.f;
        const float* wr = fcq_w + (size_t)o * Dn;
#pragma unroll 8
        for (int d = 0; d < Dn; d++) c = fmaf(wr[d], am[d], c);
        g_corr[b * Dn + o] = c;
        float sk = fc_b[o];
        const float* fr = fc_w + (size_t)o * 2 * Dn;
#pragma unroll 8
        for (int d = 0; d < Dn; d++) {
            sk = fmaf(fr[d], am[d], sk);
            sk = fmaf(fr[Dn + d], as[d], sk);
        }
        out[(size_t)Bn * Ln * Dn + b * Dn + o] = sk;
    }
}

// ---------------- 9. out1[b,l,o] = v[b,o,l] + corr[b,o]  (tiled transpose) ----------------
__global__ void k_out(const float* __restrict__ v, float* __restrict__ out) {
    __shared__ float tile[32][33];
    int b = blockIdx.z;
    int l0 = blockIdx.x * 32;
    int o0 = blockIdx.y * 32;
    int tx = threadIdx.x, ty = threadIdx.y;  // 32 x 8
#pragma unroll
    for (int i = 0; i < 4; i++) {
        int o = o0 + ty + i * 8;
        tile[ty + i * 8][tx] = v[((size_t)b * Dn + o) * Ln + l0 + tx] + g_corr[b * Dn + o];
    }
    __syncthreads();
#pragma unroll
    for (int i = 0; i < 4; i++) {
        int l = l0 + ty + i * 8;
        out[((size_t)b * Ln + l) * Dn + o0 + tx] = tile[tx][ty + i * 8];
    }
}

// ---------------- launcher ----------------
extern "C" void kernel_launch(void* const* d_in, const int* in_sizes, int n_in,
                              void* d_out, int out_size) {
    const float* v     = (const float*)d_in[0];
    const float* ln_g  = (const float*)d_in[1];
    const float* ln_b  = (const float*)d_in[2];
    const float* wk    = (const float*)d_in[3];
    const float* wq    = (const float*)d_in[4];
    const float* fcq_w = (const float*)d_in[5];
    const float* fc_w  = (const float*)d_in[6];
    const float* fc_b  = (const float*)d_in[7];
    float* out = (float*)d_out;

    k_ln_stats<<<Bn * Ln / 256, 256>>>(v);
    k_scalars<<<Bn, 256>>>();
    k_rowsums<<<Bn * Dn, 256>>>(v, 0);
    k_qp<<<Bn, 256>>>(wk, wq, ln_g, ln_b);
    k_scores<<<Bn * Ln / 256, 256>>>(v);
    k_softmax<<<Bn, 1024>>>();
    k_rowsums<<<Bn * Dn, 256>>>(v, 1);
    k_finalize<<<Bn, 256>>>(fcq_w, fc_w, fc_b, ln_g, ln_b, out);
    k_out<<<dim3(Ln / 32, Dn / 32, Bn), dim3(32, 8)>>>(v, out);
}

// round 2
// speedup vs baseline: 1.1157x; 1.1157x over previous
#include <cuda_runtime.h>
#include <cfloat>
#include <math.h>

#define Bn 64
#define Dn 256
#define Ln 4096
#define DKn 128
#define LN_EPS 1e-6f
#define EPS_CLIP 1e-10f

#define CH1 64                 // l-chunk per pass1 block
#define NCH (Ln / CH1)         // 64 chunks per batch

// ---------------- scratch (static device globals; no allocation) ----------------
__device__ float g_mu[Bn * Ln];
__device__ float g_rsig[Bn * Ln];
__device__ float g_scores[Bn * Ln];
__device__ float g_w[Bn * Ln];
__device__ float g_PU[Bn * NCH * 3 * Dn];   // per-chunk partials of U1,U2,U3
__device__ float g_Psmr[Bn * NCH];
__device__ float g_Ps22[Bn * NCH];
__device__ float g_R1[Bn * Dn], g_R2[Bn * Dn], g_R3[Bn * Dn];
__device__ float g_gp[Bn * Dn];
__device__ float g_corr[Bn * Dn];
__device__ float g_Cb[Bn], g_Gp[Bn], g_A[Bn], g_M2[Bn];

// ---------------- reduction helpers ----------------
__device__ __forceinline__ float warpSum(float v) {
#pragma unroll
    for (int o = 16; o; o >>= 1) v += __shfl_xor_sync(0xffffffffu, v, o);
    return v;
}
__device__ __forceinline__ float warpMax(float v) {
#pragma unroll
    for (int o = 16; o; o >>= 1) v = fmaxf(v, __shfl_xor_sync(0xffffffffu, v, o));
    return v;
}
__device__ __forceinline__ float bSum(float v) {
    __shared__ float sh[32];
    int lane = threadIdx.x & 31, w = threadIdx.x >> 5;
    int nw = (blockDim.x + 31) >> 5;
    v = warpSum(v);
    if (lane == 0) sh[w] = v;
    __syncthreads();
    if (w == 0) {
        float x = (lane < nw) ? sh[lane] : 0.0f;
        x = warpSum(x);
        if (lane == 0) sh[0] = x;
    }
    __syncthreads();
    float r = sh[0];
    __syncthreads();
    return r;
}
__device__ __forceinline__ float bMax(float v) {
    __shared__ float sh[32];
    int lane = threadIdx.x & 31, w = threadIdx.x >> 5;
    int nw = (blockDim.x + 31) >> 5;
    v = warpMax(v);
    if (lane == 0) sh[w] = v;
    __syncthreads();
    if (w == 0) {
        float x = (lane < nw) ? sh[lane] : -FLT_MAX;
        x = warpMax(x);
        if (lane == 0) sh[0] = x;
    }
    __syncthreads();
    float r = sh[0];
    __syncthreads();
    return r;
}

// ---------------- 1. fused: LN stats + unweighted rowsum partials ----------------
// One block per (b, chunk of 64 l). Tile of v [256 d x 64 l] staged in dynamic smem.
// Phase A: column-wise coalesced DRAM read -> mu/rsig per l + tile stash.
// Phase B: row-wise smem re-read -> partial U1/U2/U3 per d for this chunk.
__global__ void k_pass1(const float* __restrict__ v) {
    extern __shared__ float sm[];
    float* tile = sm;                 // 256*64
    float* s_mu = sm + Dn * CH1;      // 64
    float* s_rs = s_mu + CH1;         // 64
    float* sred = s_rs + CH1;         // 1024 (8*64*2)

    int tid = threadIdx.x;            // 512
    int b = blockIdx.x >> 6;          // NCH == 64
    int ch = blockIdx.x & 63;
    int l0 = ch * CH1;
    int ll = tid & 63;
    int h = tid >> 6;                 // 0..7, each handles 32 d's

    const float* base = v + (size_t)b * Dn * Ln + l0 + ll;
    float s = 0.f, s2 = 0.f;
#pragma unroll 8
    for (int dd = 0; dd < 32; dd++) {
        int d = h * 32 + dd;
        float x = base[(size_t)d * Ln];
        tile[d * CH1 + ll] = x;
        s += x;
        s2 += x * x;
    }
    sred[h * CH1 + ll] = s;
    sred[512 + h * CH1 + ll] = s2;
    __syncthreads();

    if (tid < CH1) {
        float ss = 0.f, ss2 = 0.f;
#pragma unroll
        for (int hh = 0; hh < 8; hh++) {
            ss  += sred[hh * CH1 + tid];
            ss2 += sred[512 + hh * CH1 + tid];
        }
        float mu = ss * (1.0f / Dn);
        float var = ss2 * (1.0f / Dn) - mu * mu;
        float rs = rsqrtf(var + LN_EPS);
        s_mu[tid] = mu;
        s_rs[tid] = rs;
        g_mu[b * Ln + l0 + tid] = mu;
        g_rsig[b * Ln + l0 + tid] = rs;
        float mr = mu * rs;
        sred[tid] = mr;            // reuse (own-thread read-before-write only)
        sred[CH1 + tid] = mr * mr;
    }
    __syncthreads();
    if (tid < 32) {
        float a = sred[tid] + sred[32 + tid];
        a = warpSum(a);
        if (tid == 0) g_Psmr[blockIdx.x] = a;
    } else if (tid < 64) {
        int u = tid - 32;
        float a = sred[CH1 + u] + sred[CH1 + 32 + u];
        a = warpSum(a);
        if (u == 0) g_Ps22[blockIdx.x] = a;
    }
    __syncthreads();

    // Phase B: per-d sums over this chunk's 64 l's
    int w = tid >> 5, lane = tid & 31;   // 16 warps
#pragma unroll
    for (int i = 0; i < 16; i++) {
        int d = i * 16 + w;
        float s1 = 0.f, t2 = 0.f, t3 = 0.f;
#pragma unroll
        for (int j = 0; j < 2; j++) {
            int l = j * 32 + lane;
            float x = tile[d * CH1 + l];
            float r = s_rs[l], a = s_mu[l];
            float xr = x * r;
            s1 += xr;
            t2 = fmaf(xr, xr, t2);       // x^2 r^2
            t3 = fmaf(xr, a * r, t3);    // x mu r^2
        }
        s1 = warpSum(s1);
        t2 = warpSum(t2);
        t3 = warpSum(t3);
        if (lane == 0) {
            int bc = blockIdx.x;
            g_PU[(bc * 3 + 0) * Dn + d] = s1;
            g_PU[(bc * 3 + 1) * Dn + d] = t2;
            g_PU[(bc * 3 + 2) * Dn + d] = t3;
        }
    }
}

// ---------------- 2. per batch: reduce partials, batch mean/std, q, p ----------------
__global__ void k_qp(const float* __restrict__ wk, const float* __restrict__ wq,
                     const float* __restrict__ ln_g, const float* __restrict__ ln_b) {
    int b = blockIdx.x;
    int t = threadIdx.x;  // 256
    int w = t >> 5, lane = t & 31;
    __shared__ float ms[2 * Dn];
    __shared__ float qv[DKn];
    __shared__ float s_sc[2];

    // reduce U partials over chunks (coalesced over t)
    float U1 = 0.f, U2 = 0.f, U3 = 0.f;
#pragma unroll 8
    for (int c = 0; c < NCH; c++) {
        int bc = b * NCH + c;
        U1 += g_PU[(bc * 3 + 0) * Dn + t];
        U2 += g_PU[(bc * 3 + 1) * Dn + t];
        U3 += g_PU[(bc * 3 + 2) * Dn + t];
    }
    if (w == 0) {
        float a = g_Psmr[b * NCH + lane] + g_Psmr[b * NCH + 32 + lane];
        a = warpSum(a);
        if (lane == 0) s_sc[0] = a;
    } else if (w == 1) {
        float a = g_Ps22[b * NCH + lane] + g_Ps22[b * NCH + 32 + lane];
        a = warpSum(a);
        if (lane == 0) s_sc[1] = a;
    }
    __syncthreads();
    float smr = s_sc[0], sm2r2 = s_sc[1];

    {
        int d = t;
        float g = ln_g[d], be = ln_b[d];
        float S1 = g * (U1 - smr) + (float)Ln * be;
        float S2 = g * g * (U2 - 2.0f * U3 + sm2r2) + 2.0f * g * be * (U1 - smr) + (float)Ln * be * be;
        float mean = S1 * (1.0f / Ln);
        float var = S2 * (1.0f / Ln) - mean * mean;
        float sd = sqrtf(fmaxf(var, EPS_CLIP));
        ms[d] = mean;
        ms[Dn + d] = sd;
    }
    __syncthreads();

    // q = wq @ [mean; std], warp-per-output with coalesced lane reads
#pragma unroll
    for (int i = 0; i < 16; i++) {
        int k = w * 16 + i;
        float acc = 0.f;
        const float* wr = wq + (size_t)k * 2 * Dn;
#pragma unroll
        for (int e = 0; e < 16; e++)
            acc = fmaf(wr[e * 32 + lane], ms[e * 32 + lane], acc);
        acc = warpSum(acc);
        if (lane == 0) qv[k] = acc;
    }
    __syncthreads();

    // p[d] = sum_k wk[k,d] * q[k]  (coalesced over d = t)
    float p = 0.f;
#pragma unroll 8
    for (int k2 = 0; k2 < DKn; k2++) p = fmaf(wk[k2 * Dn + t], qv[k2], p);
    p *= rsqrtf((float)DKn);

    float gp = ln_g[t] * p;
    g_gp[b * Dn + t] = gp;
    float cb = bSum(ln_b[t] * p);
    float gpsum = bSum(gp);
    if (t == 0) { g_Cb[b] = cb; g_Gp[b] = gpsum; }
}

// ---------------- 3. scores[b,l] = rsig*(sum_d v[b,d,l]*gp[b,d] - mu*Gp) + Cb ----------------
__global__ void k_scores(const float* __restrict__ v) {
    __shared__ float sgp[Dn];
    int b = blockIdx.x / (Ln / 256);
    int l = (blockIdx.x % (Ln / 256)) * 256 + threadIdx.x;
    sgp[threadIdx.x] = g_gp[b * Dn + threadIdx.x];
    __syncthreads();
    const float* col = v + (size_t)b * Dn * Ln + l;
    float acc = 0.f;
#pragma unroll 8
    for (int d = 0; d < Dn; d++) acc = fmaf(col[(size_t)d * Ln], sgp[d], acc);
    float a = g_mu[b * Ln + l], r = g_rsig[b * Ln + l];
    g_scores[b * Ln + l] = r * (acc - a * g_Gp[b]) + g_Cb[b];
}

// ---------------- 4. softmax over L per batch; also A, M2 ----------------
__global__ void k_softmax() {
    int b = blockIdx.x;
    int t = threadIdx.x;  // 1024
    float s[4];
    float m = -FLT_MAX;
#pragma unroll
    for (int i = 0; i < 4; i++) {
        s[i] = g_scores[b * Ln + i * 1024 + t];
        m = fmaxf(m, s[i]);
    }
    float M = bMax(m);
    float e[4];
    float se = 0.f, sar = 0.f, sa2 = 0.f;
#pragma unroll
    for (int i = 0; i < 4; i++) {
        e[i] = __expf(s[i] - M);
        se += e[i];
        int l = i * 1024 + t;
        float a = g_mu[b * Ln + l], r = g_rsig[b * Ln + l];
        sar = fmaf(e[i], a * r, sar);
        sa2 = fmaf(e[i], a * a * r * r, sa2);
    }
    float SE = bSum(se);
    float SAR = bSum(sar);
    float SA2 = bSum(sa2);
    float inv = 1.0f / SE;
#pragma unroll
    for (int i = 0; i < 4; i++) g_w[b * Ln + i * 1024 + t] = e[i] * inv;
    if (t == 0) { g_A[b] = SAR * inv; g_M2[b] = SA2 * inv; }
}

// ---------------- 5. weighted rowsums: 16 d's per block, coeffs staged in smem ----------------
__global__ void __launch_bounds__(512) k_attsums(const float* __restrict__ v) {
    __shared__ float c1[2048], c2[2048], c3[2048];
    int b = blockIdx.x >> 4;
    int dg = blockIdx.x & 15;
    int tid = threadIdx.x;            // 512
    int w = tid >> 5, lane = tid & 31;
    int d = dg * 16 + w;
    const float* vp = v + ((size_t)(b * Dn + d)) * Ln;
    const float* wp = g_w + b * Ln;
    const float* rp = g_rsig + b * Ln;
    const float* ap = g_mu + b * Ln;
    float s1 = 0.f, s2 = 0.f, s3 = 0.f;

#pragma unroll
    for (int chk = 0; chk < 2; chk++) {
        int lb = chk * 2048;
#pragma unroll
        for (int k = 0; k < 4; k++) {
            int l = lb + k * 512 + tid;
            float wg = wp[l], r = rp[l], a = ap[l];
            float cc1 = wg * r;
            float cc2 = cc1 * r;
            c1[k * 512 + tid] = cc1;
            c2[k * 512 + tid] = cc2;
            c3[k * 512 + tid] = cc2 * a;
        }
        __syncthreads();
#pragma unroll 8
        for (int j = 0; j < 64; j++) {
            int l = j * 32 + lane;
            float x = vp[lb + l];
            s1 = fmaf(x, c1[l], s1);
            s2 = fmaf(x * x, c2[l], s2);
            s3 = fmaf(x, c3[l], s3);
        }
        __syncthreads();
    }
    s1 = warpSum(s1);
    s2 = warpSum(s2);
    s3 = warpSum(s3);
    if (lane == 0) {
        int row = b * Dn + d;
        g_R1[row] = s1;
        g_R2[row] = s2;
        g_R3[row] = s3;
    }
}

// ---------------- 6. att stats -> corr + skip_conn ----------------
__global__ void k_finalize(const float* __restrict__ fcq_w, const float* __restrict__ fc_w,
                           const float* __restrict__ fc_b, const float* __restrict__ ln_g,
                           const float* __restrict__ ln_b, float* __restrict__ out) {
    int b = blockIdx.x;
    int t = threadIdx.x;  // 256
    __shared__ float am[Dn], as[Dn];
    {
        int d = t;
        float g = ln_g[d], be = ln_b[d];
        float R1 = g_R1[b * Dn + d], R2 = g_R2[b * Dn + d], R3 = g_R3[b * Dn + d];
        float A = g_A[b], M2 = g_M2[b];
        float mean = g * (R1 - A) + be;
        float E2 = g * g * (R2 - 2.0f * R3 + M2) + 2.0f * g * be * (R1 - A) + be * be;
        float var = E2 - mean * mean;
        am[d] = mean;
        as[d] = sqrtf(fmaxf(var, EPS_CLIP));
    }
    __syncthreads();
    {
        int o = t;
        float c = 0.f;
        const float* wr = fcq_w + (size_t)o * Dn;
#pragma unroll 8
        for (int d = 0; d < Dn; d++) c = fmaf(wr[d], am[d], c);
        g_corr[b * Dn + o] = c;
        float sk = fc_b[o];
        const float* fr = fc_w + (size_t)o * 2 * Dn;
#pragma unroll 8
        for (int d = 0; d < Dn; d++) {
            sk = fmaf(fr[d], am[d], sk);
            sk = fmaf(fr[Dn + d], as[d], sk);
        }
        out[(size_t)Bn * Ln * Dn + b * Dn + o] = sk;
    }
}

// ---------------- 7. out1[b,l,o] = v[b,o,l] + corr[b,o]  (128l x 32o tile, float4 stores) ----------------
__global__ void k_out(const float* __restrict__ v, float* __restrict__ out) {
    __shared__ float tile[32 * 129];
    int b = blockIdx.z;
    int l0 = blockIdx.x * 128;
    int o0 = blockIdx.y * 32;
    int tid = threadIdx.x;          // 256
    int w = tid >> 5, lane = tid & 31;

#pragma unroll
    for (int i = 0; i < 4; i++) {
        int ol = w + 8 * i;
        int o = o0 + ol;
        float c = g_corr[b * Dn + o];
        const float* vr = v + ((size_t)(b * Dn + o)) * Ln + l0;
#pragma unroll
        for (int j = 0; j < 4; j++)
            tile[ol * 129 + j * 32 + lane] = vr[j * 32 + lane] + c;
    }
    __syncthreads();

    int o4 = tid & 7;       // 8 float4 groups across o
    int lq = tid >> 3;      // 0..31
#pragma unroll
    for (int i = 0; i < 4; i++) {
        int l = i * 32 + lq;
        float4 y;
        y.x = tile[(o4 * 4 + 0) * 129 + l];
        y.y = tile[(o4 * 4 + 1) * 129 + l];
        y.z = tile[(o4 * 4 + 2) * 129 + l];
        y.w = tile[(o4 * 4 + 3) * 129 + l];
        *reinterpret_cast<float4*>(out + ((size_t)b * Ln + l0 + l) * Dn + o0 + o4 * 4) = y;
    }
}

// ---------------- launcher ----------------
extern "C" void kernel_launch(void* const* d_in, const int* in_sizes, int n_in,
                              void* d_out, int out_size) {
    const float* v     = (const float*)d_in[0];
    const float* ln_g  = (const float*)d_in[1];
    const float* ln_b  = (const float*)d_in[2];
    const float* wk    = (const float*)d_in[3];
    const float* wq    = (const float*)d_in[4];
    const float* fcq_w = (const float*)d_in[5];
    const float* fc_w  = (const float*)d_in[6];
    const float* fc_b  = (const float*)d_in[7];
    float* out = (float*)d_out;

    const int p1_smem = (Dn * CH1 + 2 * CH1 + 1024) * 4;  // 70144 B
    cudaFuncSetAttribute(k_pass1, cudaFuncAttributeMaxDynamicSharedMemorySize, p1_smem);

    k_pass1<<<Bn * NCH, 512, p1_smem>>>(v);
    k_qp<<<Bn, 256>>>(wk, wq, ln_g, ln_b);
    k_scores<<<Bn * Ln / 256, 256>>>(v);
    k_softmax<<<Bn, 1024>>>();
    k_attsums<<<Bn * 16, 512>>>(v);
    k_finalize<<<Bn, 256>>>(fcq_w, fc_w, fc_b, ln_g, ln_b, out);
    k_out<<<dim3(Ln / 128, Dn / 32, Bn), 256>>>(v, out);
}